// round 8
// baseline (speedup 1.0000x reference)
#include <cuda_runtime.h>
#include <cstdint>

#define NEGV (-1e30f)
#define LOG2E 1.4426950408889634f
#define LN2   0.6931471805599453f
#define CHUNK 8
#define NCHUNK 16
#define GROWS  8          // (t,n)-rows per gather block

// Static device scratch (allocation APIs are forbidden).
__device__ float    g_emit[12u * 1024u * 1024u];  // lane-major log2 emissions
__device__ float    g_alpha[1024 * 224];
__device__ float    g_gamma[1024 * 224];
__device__ float    g_tot[1024];
__device__ unsigned g_chunk[NCHUNK];               // gather progress, zero-init
__device__ unsigned g_fb_ctr;                      // fb completion counter

__device__ __forceinline__ float ex2f(float x) {
    float y; asm("ex2.approx.ftz.f32 %0, %1;" : "=f"(y) : "f"(x)); return y;
}
__device__ __forceinline__ float lg2f(float x) {
    float y; asm("lg2.approx.ftz.f32 %0, %1;" : "=f"(y) : "f"(x)); return y;
}
__device__ __forceinline__ float lae3(float x0, float x1, float x2) {
    float hi = fmaxf(x0, fmaxf(x1, x2));
    float lo = fminf(x0, fminf(x1, x2));
    float md = fmaxf(fminf(x0, x1), fminf(fmaxf(x0, x1), x2));
    return hi + lg2f(1.0f + ex2f(md - hi) + ex2f(lo - hi));
}

__device__ __forceinline__ unsigned chunk_rows(int c, int CS, int T, int N) {
    int lo = c * CS;
    int hi = lo + CS; if (hi > T) hi = T;
    int w  = hi - lo; if (w < 0) w = 0;
    return (unsigned)(w * N);
}
// fwd: ensure chunks 0..c done. `ready` meaningful on lane 0 only.
__device__ __forceinline__ void ensure_up(int c, int& ready, int CS, int T, int N) {
    if (c > NCHUNK - 1) c = NCHUNK - 1;
    if (threadIdx.x == 0) {
        while (ready < c) {
            int nc = ready + 1;
            if (*((volatile unsigned*)&g_chunk[nc]) >= chunk_rows(nc, CS, T, N))
                ready = nc;
            else __nanosleep(128);
        }
    }
    __syncwarp();
}
// bwd: ensure chunks c..NCHUNK-1 done.
__device__ __forceinline__ void ensure_dn(int c, int& ready, int CS, int T, int N) {
    if (c < 0) c = 0;
    if (threadIdx.x == 0) {
        while (ready > c) {
            int nc = ready - 1;
            if (*((volatile unsigned*)&g_chunk[nc]) >= chunk_rows(nc, CS, T, N))
                ready = nc;
            else __nanosleep(128);
        }
    }
    __syncwarp();
}

__device__ __forceinline__ void issue_chunk(const float* eb, size_t tstride,
                                            float (*sm)[CHUNK][256], int lane,
                                            int buf, int i0, int imax,
                                            bool descending, int tbase) {
#pragma unroll
    for (int j = 0; j < CHUNK; ++j) {
        int ii = i0 + j;
        if (ii > imax) ii = imax;
        int tt = descending ? (tbase - ii) : ii;
        const float* src = eb + (size_t)tt * tstride;
        uint32_t dst = (uint32_t)__cvta_generic_to_shared(&sm[buf][j][lane * 8]);
        asm volatile(
            "cp.async.cg.shared.global [%0], [%1], 16;\n\t"
            "cp.async.cg.shared.global [%2], [%3], 16;\n\t"
            :: "r"(dst), "l"(src), "r"(dst + 16), "l"(src + 4));
    }
    asm volatile("cp.async.commit_group;" ::: "memory");
}

// ===========================================================================
// ONE fused kernel: blocks [0, 2N) = fb (forward/backward recursion, 1 warp),
// blocks [2N, ...) = gather (8 rows each, ends-first order, flags progress).
// Last fb block combines + reduces + resets counters.
// ===========================================================================
__global__ void __launch_bounds__(256, 1)
mega_kernel(const float* __restrict__ lp,
            const int*   __restrict__ targets,
            const int*   __restrict__ il,
            const int*   __restrict__ tl,
            float*       __restrict__ out,
            int N, int C, int L, int T, int CS) {
    __shared__ float sm[2][CHUNK][256];
    const int S = 2 * L + 1;

    if (blockIdx.x >= (unsigned)(2 * N)) {
        // ------------------------- gather role -------------------------
        const int g  = blockIdx.x - 2 * N;
        const int j    = threadIdx.x;       // 0..255
        const int lane = j >> 3;
        const int idx  = j & 7;
        const int s    = 7 * lane + idx;

        int ts[GROWS]; bool ok[GROWS];
#pragma unroll
        for (int k = 0; k < GROWS; ++k) {
            int r = g * GROWS + k;
            ok[k] = (r < T * N);
            int zt = 0, n = 0;
            if (ok[k]) { zt = r / N; n = r % N; }
            int t = (zt & 1) ? (T - 1 - (zt >> 1)) : (zt >> 1);
            ts[k] = t;
            if (ok[k]) {
                int tn = t * N + n;
                int lab = 0;
                if (idx < 7 && s < S && (s & 1))
                    lab = __ldg(&targets[n * L + (s >> 1)]);
                float e = NEGV;
                if (idx < 7 && s < S)
                    e = __ldg(lp + (size_t)tn * C + lab) * LOG2E;
                g_emit[(size_t)tn * 256 + j] = e;
            }
        }
        __syncthreads();
        __threadfence();
        if (threadIdx.x == 0) {
#pragma unroll
            for (int k = 0; k < GROWS; ++k)
                if (ok[k]) atomicAdd(&g_chunk[ts[k] / CS], 1u);
        }
        return;
    }

    // --------------------------- fb role ---------------------------
    if (threadIdx.x >= 32) return;          // single warp per fb block

    const bool fwd = (blockIdx.x < (unsigned)N);
    const int  n    = fwd ? blockIdx.x : (blockIdx.x - N);
    const int  lane = threadIdx.x;

    const int ilen  = il[n];
    const int s_end = 2 * tl[n];
    const int m     = (ilen - 1) >> 1;

    const float* eb      = g_emit + (size_t)n * 256 + lane * 8;
    const size_t tstride = (size_t)N * 256;

    float a[7];

    if (fwd) {
        int ready = -1;
        bool skip[7];
#pragma unroll
        for (int i = 0; i < 7; ++i) {
            int s = 7 * lane + i;
            skip[i] = false;
            if (s < S && (s & 1) && s >= 3)
                skip[i] = (__ldg(&targets[n * L + (s >> 1)]) !=
                           __ldg(&targets[n * L + (s >> 1) - 1]));
        }
        ensure_up(0, ready, CS, T, N);
#pragma unroll
        for (int i = 0; i < 7; ++i) {
            int s = 7 * lane + i;
            a[i] = (s <= 1) ? __ldg(eb + i) : NEGV;
        }
        if (m >= 1) {
            int mt0 = CHUNK     < m ? CHUNK     : m;
            int mt1 = 2 * CHUNK < m ? 2 * CHUNK : m;
            ensure_up(mt0 / CS, ready, CS, T, N);
            issue_chunk(eb, tstride, sm, lane, 0, 1, m, false, 0);
            ensure_up(mt1 / CS, ready, CS, T, N);
            issue_chunk(eb, tstride, sm, lane, 1, 1 + CHUNK, m, false, 0);
            int t = 1, buf = 0;
            while (t <= m) {
                asm volatile("cp.async.wait_group 1;" ::: "memory");
                __syncwarp();
                float4 E0[CHUNK], E1[CHUNK];
#pragma unroll
                for (int j = 0; j < CHUNK; ++j) {
                    E0[j] = *(const float4*)&sm[buf][j][lane * 8];
                    E1[j] = *(const float4*)&sm[buf][j][lane * 8 + 4];
                }
                __syncwarp();
                int mt = t + 3 * CHUNK - 1; if (mt > m) mt = m;
                ensure_up(mt / CS, ready, CS, T, N);
                issue_chunk(eb, tstride, sm, lane, buf, t + 2 * CHUNK, m, false, 0);
                buf ^= 1;
#pragma unroll
                for (int j = 0; j < CHUNK; ++j) {
                    if (t <= m) {
                        float e[7] = {E0[j].x, E0[j].y, E0[j].z, E0[j].w,
                                      E1[j].x, E1[j].y, E1[j].z};
                        float h6 = __shfl_up_sync(0xffffffffu, a[6], 1);
                        float h5 = __shfl_up_sync(0xffffffffu, a[5], 1);
                        if (lane == 0) { h5 = NEGV; h6 = NEGV; }
#pragma unroll
                        for (int i = 6; i >= 0; --i) {
                            float x0 = a[i];
                            float x1 = (i >= 1) ? a[i - 1] : h6;
                            float x2 = (i >= 2) ? a[i - 2] : ((i == 1) ? h6 : h5);
                            x2 = skip[i] ? x2 : NEGV;
                            a[i] = lae3(x0, x1, x2) + e[i];
                        }
                        ++t;
                    }
                }
            }
        }
#pragma unroll
        for (int i = 0; i < 7; ++i)
            g_alpha[n * 224 + 7 * lane + i] = a[i];
    } else {
        int ready = NCHUNK;
        bool bskip[7];
#pragma unroll
        for (int i = 0; i < 7; ++i) {
            int s = 7 * lane + i;
            bskip[i] = false;
            if (s < S && (s & 1) && (s >> 1) + 1 <= L - 1)
                bskip[i] = (__ldg(&targets[n * L + (s >> 1)]) !=
                            __ldg(&targets[n * L + (s >> 1) + 1]));
        }
        if (ilen == 1) {
            ensure_dn((ilen - 1) / CS, ready, CS, T, N);
#pragma unroll
            for (int i = 0; i < 7; ++i) {
                int s = 7 * lane + i;
                a[i] = (s == s_end || (s_end >= 1 && s == s_end - 1)) ? 0.0f : NEGV;
            }
        } else {
            ensure_dn((ilen - 1) / CS, ready, CS, T, N);
#pragma unroll
            for (int i = 0; i < 7; ++i) {
                int s = 7 * lane + i;
                float e = __ldg(eb + (size_t)(ilen - 1) * tstride + i);
                a[i] = (s == s_end || (s_end >= 1 && s == s_end - 1)) ? e : NEGV;
            }
            const int K = ilen - 2 - m;
            if (K >= 1) {
                int d0 = CHUNK     < K ? CHUNK     : K;
                int d1 = 2 * CHUNK < K ? 2 * CHUNK : K;
                ensure_dn((ilen - 1 - d0) / CS, ready, CS, T, N);
                issue_chunk(eb, tstride, sm, lane, 0, 1, K, true, ilen - 1);
                ensure_dn((ilen - 1 - d1) / CS, ready, CS, T, N);
                issue_chunk(eb, tstride, sm, lane, 1, 1 + CHUNK, K, true, ilen - 1);
                int k = 1, buf = 0;
                while (k <= K) {
                    asm volatile("cp.async.wait_group 1;" ::: "memory");
                    __syncwarp();
                    float4 E0[CHUNK], E1[CHUNK];
#pragma unroll
                    for (int j = 0; j < CHUNK; ++j) {
                        E0[j] = *(const float4*)&sm[buf][j][lane * 8];
                        E1[j] = *(const float4*)&sm[buf][j][lane * 8 + 4];
                    }
                    __syncwarp();
                    int dd = k + 3 * CHUNK - 1; if (dd > K) dd = K;
                    ensure_dn((ilen - 1 - dd) / CS, ready, CS, T, N);
                    issue_chunk(eb, tstride, sm, lane, buf, k + 2 * CHUNK, K,
                                true, ilen - 1);
                    buf ^= 1;
#pragma unroll
                    for (int j = 0; j < CHUNK; ++j) {
                        if (k <= K) {
                            float e[7] = {E0[j].x, E0[j].y, E0[j].z, E0[j].w,
                                          E1[j].x, E1[j].y, E1[j].z};
                            float h0 = __shfl_down_sync(0xffffffffu, a[0], 1);
                            float h1 = __shfl_down_sync(0xffffffffu, a[1], 1);
                            if (lane == 31) { h0 = NEGV; h1 = NEGV; }
#pragma unroll
                            for (int i = 0; i <= 6; ++i) {
                                float x0 = a[i];
                                float x1 = (i <= 5) ? a[i + 1] : h0;
                                float x2 = (i <= 4) ? a[i + 2] : ((i == 5) ? h0 : h1);
                                x2 = bskip[i] ? x2 : NEGV;
                                a[i] = lae3(x0, x1, x2) + e[i];
                            }
                            ++k;
                        }
                    }
                }
            }
            // gamma: one transition-only step (no emission)
            {
                float h0 = __shfl_down_sync(0xffffffffu, a[0], 1);
                float h1 = __shfl_down_sync(0xffffffffu, a[1], 1);
                if (lane == 31) { h0 = NEGV; h1 = NEGV; }
                float na[7];
#pragma unroll
                for (int i = 0; i <= 6; ++i) {
                    float x0 = a[i];
                    float x1 = (i <= 5) ? a[i + 1] : h0;
                    float x2 = (i <= 4) ? a[i + 2] : ((i == 5) ? h0 : h1);
                    x2 = bskip[i] ? x2 : NEGV;
                    na[i] = lae3(x0, x1, x2);
                }
#pragma unroll
                for (int i = 0; i < 7; ++i) a[i] = na[i];
            }
        }
#pragma unroll
        for (int i = 0; i < 7; ++i)
            g_gamma[n * 224 + 7 * lane + i] = a[i];
    }

    // ---- finisher: last fb block combines, reduces, resets ----
    __threadfence();
    unsigned done = 0;
    if (lane == 0) done = (atomicAdd(&g_fb_ctr, 1u) == (unsigned)(2 * N) - 1u);
    done = __shfl_sync(0xffffffffu, done, 0);
    if (done) {
        __threadfence();
        float acc = 0.0f;
        for (int nn = 0; nn < N; ++nn) {
            float v[7];
            float mx = -3.4e38f;
#pragma unroll
            for (int k = 0; k < 7; ++k) {
                v[k] = g_alpha[nn * 224 + lane + 32 * k]
                     + g_gamma[nn * 224 + lane + 32 * k];
                mx = fmaxf(mx, v[k]);
            }
#pragma unroll
            for (int o = 16; o > 0; o >>= 1)
                mx = fmaxf(mx, __shfl_xor_sync(0xffffffffu, mx, o));
            float sum = 0.0f;
#pragma unroll
            for (int k = 0; k < 7; ++k) sum += ex2f(v[k] - mx);
#pragma unroll
            for (int o = 16; o > 0; o >>= 1)
                sum += __shfl_xor_sync(0xffffffffu, sum, o);
            float tot = (mx + lg2f(sum)) * LN2;
            if (lane == 0 && tot > -1e29f) acc += tot;
        }
        if (lane == 0) {
            out[0] = -acc;
            // reset state for the next (graph-replayed) call
            for (int c = 0; c < NCHUNK; ++c) g_chunk[c] = 0u;
            g_fb_ctr = 0u;
            __threadfence();
        }
    }
}

extern "C" void kernel_launch(void* const* d_in, const int* in_sizes, int n_in,
                              void* d_out, int out_size) {
    const float* lp      = (const float*)d_in[0];
    const int*   targets = (const int*)d_in[1];
    const int*   il      = (const int*)d_in[2];
    const int*   tl      = (const int*)d_in[3];

    const int N = in_sizes[2];
    const int L = in_sizes[1] / N;        // 100
    const int C = 1024;                   // fixed for this problem id
    const int T = in_sizes[0] / (N * C);  // 1500
    const int CS = (T + NCHUNK - 1) / NCHUNK;

    const int gather_blocks = (T * N + GROWS - 1) / GROWS;
    mega_kernel<<<2 * N + gather_blocks, 256>>>(lp, targets, il, tl,
                                                (float*)d_out, N, C, L, T, CS);
}

// round 9
// speedup vs baseline: 2.9188x; 2.9188x over previous
#include <cuda_runtime.h>
#include <cstdint>

#define NEGV (-1e30f)
#define LOG2E 1.4426950408889634f
#define LN2   0.6931471805599453f
#define CHUNK 8
#define HALO_CAP 768          // max half-recursion steps + 1 (T <= 1534)
#define SENT 0x7F800000u      // +inf bit pattern: never a valid alpha

// Static device scratch (allocation APIs are forbidden).
__device__ float    g_emit[12u * 1024u * 1024u];  // e[t][n][256], slot = state
__device__ float    g_alpha[1024 * 256];
__device__ float    g_gamma[1024 * 256];
__device__ float    g_tot[1024];
__device__ unsigned g_ctr;                         // zero-init; reset each call

__device__ __forceinline__ float ex2f(float x) {
    float y; asm("ex2.approx.ftz.f32 %0, %1;" : "=f"(y) : "f"(x)); return y;
}
__device__ __forceinline__ float lg2f(float x) {
    float y; asm("lg2.approx.ftz.f32 %0, %1;" : "=f"(y) : "f"(x)); return y;
}
__device__ __forceinline__ float lae3(float x0, float x1, float x2) {
    float hi = fmaxf(x0, fmaxf(x1, x2));
    float lo = fminf(x0, fminf(x1, x2));
    float md = fmaxf(fminf(x0, x1), fminf(fmaxf(x0, x1), x2));
    return hi + lg2f(1.0f + ex2f(md - hi) + ex2f(lo - hi));
}

__device__ __forceinline__ void st_halo(float* halo, int idx, float lo, float hi) {
    uint32_t p = (uint32_t)__cvta_generic_to_shared(halo + 2 * idx);
    asm volatile("st.volatile.shared.v2.f32 [%0], {%1, %2};"
                 :: "r"(p), "f"(lo), "f"(hi));
}
__device__ __forceinline__ float2 ld_halo(float* halo, int idx) {
    uint32_t p = (uint32_t)__cvta_generic_to_shared(halo + 2 * idx);
    float2 v;
    asm volatile("ld.volatile.shared.v2.f32 {%0, %1}, [%2];"
                 : "=f"(v.x), "=f"(v.y) : "r"(p));
    return v;
}
__device__ __forceinline__ float2 poll_halo(float* halo, int idx) {
    float2 h = ld_halo(halo, idx);
    while (__float_as_uint(h.x) == SENT) h = ld_halo(halo, idx);
    return h;
}

// ---------------------------------------------------------------------------
// Phase 1: parallel emission gather, direct state layout, log2 domain.
// ---------------------------------------------------------------------------
__global__ void gather_kernel(const float* __restrict__ lp,
                              const int*   __restrict__ targets,
                              int N, int C, int L, int S) {
    const int tn = blockIdx.x;
    const int n  = tn % N;
    const int s  = threadIdx.x;           // slot == state, 0..255
    float e = NEGV;
    if (s < S) {
        int lab = 0;
        if (s & 1) lab = __ldg(&targets[n * L + (s >> 1)]);
        e = __ldg(lp + (size_t)tn * C + lab) * LOG2E;
    }
    g_emit[(size_t)tn * 256 + s] = e;
}

// ---------------------------------------------------------------------------
// Phase 2: fwd+bwd halves; 2 warps per CTA on different SMSPs, 4 states/lane.
// One-directional producer->consumer halo through shared (volatile v2).
// ---------------------------------------------------------------------------
__device__ __forceinline__ void issue_half(const float* ebase, size_t tstride,
                                           float (*buf)[CHUNK][128], int lane,
                                           int b, int i0, int imax,
                                           bool desc, int tbase) {
#pragma unroll
    for (int j = 0; j < CHUNK; ++j) {
        int ii = i0 + j;
        if (ii > imax) ii = imax;
        int tt = desc ? (tbase - ii) : ii;
        const float* src = ebase + (size_t)tt * tstride;
        uint32_t dst = (uint32_t)__cvta_generic_to_shared(&buf[b][j][lane * 4]);
        asm volatile("cp.async.cg.shared.global [%0], [%1], 16;"
                     :: "r"(dst), "l"(src));
    }
    asm volatile("cp.async.commit_group;" ::: "memory");
}

__global__ void __launch_bounds__(64, 1)
fb_kernel(const int* __restrict__ targets,
          const int* __restrict__ il,
          const int* __restrict__ tl,
          int N, int L, int T) {
    __shared__ float sm_e[2][2][CHUNK][128];   // [warp][buf][step][state-lane]
    __shared__ float halo[2 * HALO_CAP];       // (lo, hi) per step

    const bool fwd = (blockIdx.x < (unsigned)N);
    const int  n    = fwd ? blockIdx.x : (blockIdx.x - N);
    const int  w    = threadIdx.x >> 5;        // warp 0: s 0..127, warp 1: 128..255
    const int  lane = threadIdx.x & 31;
    const int  S    = 2 * L + 1;
    const int  base = w * 128 + lane * 4;

    const int ilen  = il[n];
    const int s_end = 2 * tl[n];
    const int m     = (ilen - 1) >> 1;

    // init halo slots to sentinel
    for (int i = threadIdx.x; i < HALO_CAP; i += 64) {
        halo[2 * i]     = __uint_as_float(SENT);
        halo[2 * i + 1] = __uint_as_float(SENT);
    }
    __syncthreads();

    const float* ebase   = g_emit + (size_t)n * 256 + base;
    const size_t tstride = (size_t)N * 256;
    float (*buf)[CHUNK][128] = sm_e[w];

    float a[4];

    if (fwd) {
        bool skip[4];
#pragma unroll
        for (int i = 0; i < 4; ++i) {
            int s = base + i;
            skip[i] = false;
            if (s < S && (s & 1) && s >= 3)
                skip[i] = (__ldg(&targets[n * L + (s >> 1)]) !=
                           __ldg(&targets[n * L + (s >> 1) - 1]));
        }
        {   // t = 0
            float4 E = __ldg((const float4*)ebase);
            float e0[4] = {E.x, E.y, E.z, E.w};
#pragma unroll
            for (int i = 0; i < 4; ++i)
                a[i] = (base + i <= 1) ? e0[i] : NEGV;
        }
        if (w == 0 && lane == 31) st_halo(halo, 0, a[2], a[3]);   // alpha_0

        if (m >= 1) {
            issue_half(ebase, tstride, buf, lane, 0, 1, m, false, 0);
            issue_half(ebase, tstride, buf, lane, 1, 1 + CHUNK, m, false, 0);
            int t = 1, b = 0;
            while (t <= m) {
                asm volatile("cp.async.wait_group 1;" ::: "memory");
                __syncwarp();
                float4 E[CHUNK];
#pragma unroll
                for (int j = 0; j < CHUNK; ++j)
                    E[j] = *(const float4*)&buf[b][j][lane * 4];
                __syncwarp();
                issue_half(ebase, tstride, buf, lane, b, t + 2 * CHUNK, m, false, 0);
                b ^= 1;
#pragma unroll
                for (int j = 0; j < CHUNK; ++j) {
                    if (t <= m) {
                        float s3 = __shfl_up_sync(0xffffffffu, a[3], 1);
                        float s2 = __shfl_up_sync(0xffffffffu, a[2], 1);
                        if (lane == 0) {
                            if (w == 0) { s3 = NEGV; s2 = NEGV; }
                            else { float2 h = poll_halo(halo, t - 1);
                                   s2 = h.x; s3 = h.y; }
                        }
                        float e[4] = {E[j].x, E[j].y, E[j].z, E[j].w};
                        a[3] = lae3(a[3], a[2], skip[3] ? a[1] : NEGV) + e[3];
                        a[2] = lae3(a[2], a[1], skip[2] ? a[0] : NEGV) + e[2];
                        a[1] = lae3(a[1], a[0], skip[1] ? s3   : NEGV) + e[1];
                        a[0] = lae3(a[0], s3,   skip[0] ? s2   : NEGV) + e[0];
                        if (w == 0 && lane == 31) st_halo(halo, t, a[2], a[3]);
                        ++t;
                    }
                }
            }
        }
#pragma unroll
        for (int i = 0; i < 4; ++i) g_alpha[n * 256 + base + i] = a[i];
    } else {
        bool bskip[4];
#pragma unroll
        for (int i = 0; i < 4; ++i) {
            int s = base + i;
            bskip[i] = false;
            if (s < S && (s & 1) && (s >> 1) + 1 <= L - 1)
                bskip[i] = (__ldg(&targets[n * L + (s >> 1)]) !=
                            __ldg(&targets[n * L + (s >> 1) + 1]));
        }
        if (ilen == 1) {
#pragma unroll
            for (int i = 0; i < 4; ++i) {
                int s = base + i;
                a[i] = (s == s_end || (s_end >= 1 && s == s_end - 1)) ? 0.0f : NEGV;
            }
        } else {
            {   // init beta at t = ilen-1
                float4 E = __ldg((const float4*)(ebase + (size_t)(ilen - 1) * tstride));
                float e0[4] = {E.x, E.y, E.z, E.w};
#pragma unroll
                for (int i = 0; i < 4; ++i) {
                    int s = base + i;
                    a[i] = (s == s_end || (s_end >= 1 && s == s_end - 1))
                           ? e0[i] : NEGV;
                }
            }
            if (w == 1 && lane == 0) st_halo(halo, 0, a[0], a[1]);  // beta_0

            const int K = ilen - 2 - m;
            if (K >= 1) {
                issue_half(ebase, tstride, buf, lane, 0, 1, K, true, ilen - 1);
                issue_half(ebase, tstride, buf, lane, 1, 1 + CHUNK, K, true, ilen - 1);
                int k = 1, b = 0;
                while (k <= K) {
                    asm volatile("cp.async.wait_group 1;" ::: "memory");
                    __syncwarp();
                    float4 E[CHUNK];
#pragma unroll
                    for (int j = 0; j < CHUNK; ++j)
                        E[j] = *(const float4*)&buf[b][j][lane * 4];
                    __syncwarp();
                    issue_half(ebase, tstride, buf, lane, b, k + 2 * CHUNK, K,
                               true, ilen - 1);
                    b ^= 1;
#pragma unroll
                    for (int j = 0; j < CHUNK; ++j) {
                        if (k <= K) {
                            float d0 = __shfl_down_sync(0xffffffffu, a[0], 1);
                            float d1 = __shfl_down_sync(0xffffffffu, a[1], 1);
                            if (lane == 31) {
                                if (w == 1) { d0 = NEGV; d1 = NEGV; }
                                else { float2 h = poll_halo(halo, k - 1);
                                       d0 = h.x; d1 = h.y; }
                            }
                            float e[4] = {E[j].x, E[j].y, E[j].z, E[j].w};
                            a[0] = lae3(a[0], a[1], bskip[0] ? a[2] : NEGV) + e[0];
                            a[1] = lae3(a[1], a[2], bskip[1] ? a[3] : NEGV) + e[1];
                            a[2] = lae3(a[2], a[3], bskip[2] ? d0   : NEGV) + e[2];
                            a[3] = lae3(a[3], d0,   bskip[3] ? d1   : NEGV) + e[3];
                            if (w == 1 && lane == 0) st_halo(halo, k, a[0], a[1]);
                            ++k;
                        }
                    }
                }
            }
            {   // gamma: one transition-only step (no emission)
                float d0 = __shfl_down_sync(0xffffffffu, a[0], 1);
                float d1 = __shfl_down_sync(0xffffffffu, a[1], 1);
                if (lane == 31) {
                    if (w == 1) { d0 = NEGV; d1 = NEGV; }
                    else { float2 h = poll_halo(halo, K >= 1 ? K : 0);
                           d0 = h.x; d1 = h.y; }
                }
                a[0] = lae3(a[0], a[1], bskip[0] ? a[2] : NEGV);
                a[1] = lae3(a[1], a[2], bskip[1] ? a[3] : NEGV);
                a[2] = lae3(a[2], a[3], bskip[2] ? d0   : NEGV);
                a[3] = lae3(a[3], d0,   bskip[3] ? d1   : NEGV);
            }
        }
#pragma unroll
        for (int i = 0; i < 4; ++i) g_gamma[n * 256 + base + i] = a[i];
    }
}

// ---------------------------------------------------------------------------
// Phase 3: per-utterance logsumexp + fixed-order global reduce (finisher).
// ---------------------------------------------------------------------------
__global__ void combine_kernel(float* __restrict__ out, int N) {
    __shared__ float red[256];
    const int n = blockIdx.x;
    const int s = threadIdx.x;            // 0..255

    float v = g_alpha[n * 256 + s] + g_gamma[n * 256 + s];

    red[s] = v; __syncthreads();
    for (int o = 128; o > 0; o >>= 1) {
        if (s < o) red[s] = fmaxf(red[s], red[s + o]);
        __syncthreads();
    }
    float mx = red[0]; __syncthreads();

    float ev = (v - mx > -120.0f) ? ex2f(v - mx) : 0.0f;
    red[s] = ev; __syncthreads();
    for (int o = 128; o > 0; o >>= 1) {
        if (s < o) red[s] += red[s + o];
        __syncthreads();
    }

    if (s == 0) {
        g_tot[n] = (mx + lg2f(red[0])) * LN2;
        __threadfence();
        unsigned v2 = atomicAdd(&g_ctr, 1);
        if (v2 == (unsigned)gridDim.x - 1) {
            __threadfence();
            float acc = 0.0f;
            for (int i = 0; i < N; ++i) {
                float t = *((volatile float*)&g_tot[i]);
                if (t > -1e29f) acc += t;
            }
            out[0] = -acc;
            g_ctr = 0;
        }
    }
}

extern "C" void kernel_launch(void* const* d_in, const int* in_sizes, int n_in,
                              void* d_out, int out_size) {
    const float* lp      = (const float*)d_in[0];
    const int*   targets = (const int*)d_in[1];
    const int*   il      = (const int*)d_in[2];
    const int*   tl      = (const int*)d_in[3];

    const int N = in_sizes[2];
    const int L = in_sizes[1] / N;        // 100
    const int C = 1024;                   // fixed for this problem id
    const int T = in_sizes[0] / (N * C);  // 1500
    const int S = 2 * L + 1;              // 201

    gather_kernel<<<T * N, 256>>>(lp, targets, N, C, L, S);
    fb_kernel<<<2 * N, 64>>>(targets, il, tl, N, L, T);
    combine_kernel<<<N, 256>>>((float*)d_out, N);
}